// round 13
// baseline (speedup 1.0000x reference)
#include <cuda_runtime.h>
#include <math.h>

#define B_DIM 512
#define N_DIM 512
#define M_DIM 128
#define C_DIM 1024
#define ADDR  134
#define EPSV  1e-8f

// ---------------- scratch (device globals; no allocation allowed) ----------
__device__ float g_ks[B_DIM * M_DIM];     // beta * k / (||k||+EPS)
__device__ float g_gg[B_DIM];             // g (interpolation gate)
__device__ float g_ss[B_DIM * 3];         // shift softmax probs
__device__ float g_gamma[B_DIM];          // sharpening exponent
__device__ float g_z[B_DIM * N_DIM];      // beta * sim

__device__ __forceinline__ float softplus_f(float x) {
    return (x > 20.f) ? x : log1pf(expf(x));
}

// ============================================================================
// Kernel A: FC (4 batches / CTA, K split in 2 groups) + activations + key prep
// grid = 128, block = 288 (268 active: 2 K-groups x 134 columns)
// ============================================================================
__global__ __launch_bounds__(288) void fc_kernel(
    const float* __restrict__ ctrl,   // [B, C]
    const float* __restrict__ Wfc,    // [C, ADDR]
    const float* __restrict__ bfc)    // [ADDR]
{
    __shared__ float sctrl[4 * C_DIM];          // 16 KB
    __shared__ float spart[ADDR * 4];           // K-group partials
    __shared__ float sred[M_DIM * 4];           // ||k||^2 reduction
    __shared__ float sspec[4][6];               // beta,g,s0,s1,s2,gamma raw
    __shared__ float sscale[4];                 // beta/(||k||+EPS)

    const int tid = threadIdx.x;
    const int b0  = blockIdx.x * 4;

    // load 4 controller rows (contiguous) into smem
    const float* cb = ctrl + (size_t)b0 * C_DIM;
    for (int i = tid; i < 4 * C_DIM; i += 288) sctrl[i] = cb[i];
    __syncthreads();

    const bool active = (tid < 2 * ADDR);
    const int kg = (tid >= ADDR) ? 1 : 0;
    const int j  = tid - kg * ADDR;

    float acc[4] = {0.f, 0.f, 0.f, 0.f};
    if (active) {
        const int cbeg = kg * (C_DIM / 2);
        #pragma unroll 2
        for (int c4 = 0; c4 < (C_DIM / 2) / 4; c4++) {
            const int c = cbeg + c4 * 4;
            const float w0 = Wfc[(c + 0) * ADDR + j];
            const float w1 = Wfc[(c + 1) * ADDR + j];
            const float w2 = Wfc[(c + 2) * ADDR + j];
            const float w3 = Wfc[(c + 3) * ADDR + j];
            #pragma unroll
            for (int b = 0; b < 4; b++) {
                float4 cv = ((const float4*)(sctrl + b * C_DIM))[c / 4];
                acc[b] = fmaf(w0, cv.x, acc[b]);
                acc[b] = fmaf(w1, cv.y, acc[b]);
                acc[b] = fmaf(w2, cv.z, acc[b]);
                acc[b] = fmaf(w3, cv.w, acc[b]);
            }
        }
    }

    // combine the two K-groups
    if (active && kg == 1) {
        #pragma unroll
        for (int b = 0; b < 4; b++) spart[j * 4 + b] = acc[b];
    }
    __syncthreads();
    if (active && kg == 0) {
        const float bias = bfc[j];
        #pragma unroll
        for (int b = 0; b < 4; b++) acc[b] += spart[j * 4 + b] + bias;
        if (j < M_DIM) {
            #pragma unroll
            for (int b = 0; b < 4; b++) sred[j * 4 + b] = acc[b] * acc[b];
        } else {
            #pragma unroll
            for (int b = 0; b < 4; b++) sspec[b][j - M_DIM] = acc[b];
        }
    }
    __syncthreads();

    // reduce ||k||^2 per batch (tree over j, all threads hit the syncs)
    for (int off = 64; off > 0; off >>= 1) {
        if (active && kg == 0 && j < off) {
            #pragma unroll
            for (int b = 0; b < 4; b++)
                sred[j * 4 + b] += sred[(j + off) * 4 + b];
        }
        __syncthreads();
    }

    // per-batch scalar post-processing
    if (tid < 4) {
        const int b = tid;
        const float normk = sqrtf(sred[b]) + EPSV;
        const float beta  = softplus_f(sspec[b][0]);
        sscale[b] = beta / normk;
        g_gg[b0 + b] = 1.f / (1.f + expf(-sspec[b][1]));
        float l0 = sspec[b][2], l1 = sspec[b][3], l2 = sspec[b][4];
        float mx = fmaxf(l0, fmaxf(l1, l2));
        float e0 = expf(l0 - mx), e1 = expf(l1 - mx), e2 = expf(l2 - mx);
        float inv = 1.f / (e0 + e1 + e2);
        g_ss[(b0 + b) * 3 + 0] = e0 * inv;
        g_ss[(b0 + b) * 3 + 1] = e1 * inv;
        g_ss[(b0 + b) * 3 + 2] = e2 * inv;
        g_gamma[b0 + b] = 1.f + softplus_f(sspec[b][5]);
    }
    __syncthreads();

    // scaled key
    if (active && kg == 0 && j < M_DIM) {
        #pragma unroll
        for (int b = 0; b < 4; b++)
            g_ks[(size_t)(b0 + b) * M_DIM + j] = acc[b] * sscale[b];
    }
}

// ============================================================================
// Kernel B: z[b,n] = beta*sim = dot(mem[b,n,:], ks[b,:]) / (||mem[b,n,:]||+EPS)
// one warp -> 4 rows; grid = 8192, block = 256 (32 rows / CTA)
// ============================================================================
__global__ __launch_bounds__(256) void sim_kernel(const float* __restrict__ mem)
{
    const int lane = threadIdx.x & 31;
    const int warp = threadIdx.x >> 5;
    const int b  = blockIdx.x >> 4;                       // 16 blocks / batch
    const int n0 = ((blockIdx.x & 15) * 8 + warp) * 4;    // 4 rows / warp

    const float4 ks = ((const float4*)(g_ks + (size_t)b * M_DIM))[lane];
    const float4* mrow = (const float4*)(mem + ((size_t)b * N_DIM + n0) * M_DIM);

    float4 m0 = mrow[lane];
    float4 m1 = mrow[32 + lane];
    float4 m2 = mrow[64 + lane];
    float4 m3 = mrow[96 + lane];

    float d[4], q[4];
    d[0] = m0.x*ks.x + m0.y*ks.y + m0.z*ks.z + m0.w*ks.w;
    q[0] = m0.x*m0.x + m0.y*m0.y + m0.z*m0.z + m0.w*m0.w;
    d[1] = m1.x*ks.x + m1.y*ks.y + m1.z*ks.z + m1.w*ks.w;
    q[1] = m1.x*m1.x + m1.y*m1.y + m1.z*m1.z + m1.w*m1.w;
    d[2] = m2.x*ks.x + m2.y*ks.y + m2.z*ks.z + m2.w*ks.w;
    q[2] = m2.x*m2.x + m2.y*m2.y + m2.z*m2.z + m2.w*m2.w;
    d[3] = m3.x*ks.x + m3.y*ks.y + m3.z*ks.z + m3.w*ks.w;
    q[3] = m3.x*m3.x + m3.y*m3.y + m3.z*m3.z + m3.w*m3.w;

    #pragma unroll
    for (int r = 0; r < 4; r++) {
        #pragma unroll
        for (int off = 16; off > 0; off >>= 1) {
            d[r] += __shfl_xor_sync(0xffffffffu, d[r], off);
            q[r] += __shfl_xor_sync(0xffffffffu, q[r], off);
        }
    }
    if (lane == 0) {
        float* zp = g_z + (size_t)b * N_DIM + n0;
        zp[0] = d[0] / (sqrtf(q[0]) + EPSV);
        zp[1] = d[1] / (sqrtf(q[1]) + EPSV);
        zp[2] = d[2] / (sqrtf(q[2]) + EPSV);
        zp[3] = d[3] / (sqrtf(q[3]) + EPSV);
    }
}

// ---------------- block reductions (512 threads = 16 warps) ----------------
__device__ __forceinline__ float block_max512(float v, float* sbuf) {
    #pragma unroll
    for (int off = 16; off > 0; off >>= 1)
        v = fmaxf(v, __shfl_xor_sync(0xffffffffu, v, off));
    const int lane = threadIdx.x & 31, wp = threadIdx.x >> 5;
    if (lane == 0) sbuf[wp] = v;
    __syncthreads();
    if (wp == 0) {
        float x = (lane < 16) ? sbuf[lane] : -3.4e38f;
        #pragma unroll
        for (int off = 8; off > 0; off >>= 1)
            x = fmaxf(x, __shfl_xor_sync(0xffffffffu, x, off));
        if (lane == 0) sbuf[0] = x;
    }
    __syncthreads();
    float r = sbuf[0];
    __syncthreads();
    return r;
}

__device__ __forceinline__ float block_sum512(float v, float* sbuf) {
    #pragma unroll
    for (int off = 16; off > 0; off >>= 1)
        v += __shfl_xor_sync(0xffffffffu, v, off);
    const int lane = threadIdx.x & 31, wp = threadIdx.x >> 5;
    if (lane == 0) sbuf[wp] = v;
    __syncthreads();
    if (wp == 0) {
        float x = (lane < 16) ? sbuf[lane] : 0.f;
        #pragma unroll
        for (int off = 8; off > 0; off >>= 1)
            x += __shfl_xor_sync(0xffffffffu, x, off);
        if (lane == 0) sbuf[0] = x;
    }
    __syncthreads();
    float r = sbuf[0];
    __syncthreads();
    return r;
}

// ============================================================================
// Kernel C: softmax(z) -> interpolate -> circular shift -> sharpen -> w
// grid = 512 (batch), block = 512 (n)
// ============================================================================
__global__ __launch_bounds__(512) void addr_kernel(
    const float* __restrict__ prev_w,  // [B, N]
    float* __restrict__ out_w)         // [B, N] (region of d_out)
{
    __shared__ float swg[N_DIM];
    __shared__ float sbuf[16];

    const int b = blockIdx.x;
    const int n = threadIdx.x;

    float z = g_z[(size_t)b * N_DIM + n];
    const float zmax = block_max512(z, sbuf);
    float e = expf(z - zmax);
    const float esum = block_sum512(e, sbuf);
    const float wc = e / esum;

    const float g  = g_gg[b];
    const float wg = g * wc + (1.f - g) * prev_w[(size_t)b * N_DIM + n];
    swg[n] = wg;
    __syncthreads();

    const float s0 = g_ss[b * 3 + 0];
    const float s1 = g_ss[b * 3 + 1];
    const float s2 = g_ss[b * 3 + 2];
    const float ws = s0 * swg[(n + N_DIM - 1) & (N_DIM - 1)]
                   + s1 * wg
                   + s2 * swg[(n + 1) & (N_DIM - 1)];

    const float gamma = g_gamma[b];
    const float wp = powf(ws, gamma);
    const float denom = block_sum512(wp, sbuf) + EPSV;
    out_w[(size_t)b * N_DIM + n] = wp / denom;
}

// ============================================================================
// Kernel D: read_vec[b,m] = sum_n w[b,n] * mem[b,n,m]
// grid = 512 (batch), block = 512; 16 n-stripes x 32 float4 lanes
// ============================================================================
__global__ __launch_bounds__(512) void read_kernel(
    const float* __restrict__ mem,
    const float* __restrict__ w_in,     // [B, N]
    float* __restrict__ read_out)       // [B, M]
{
    __shared__ float  sw[N_DIM];
    __shared__ float4 sacc[16][32];

    const int b   = blockIdx.x;
    const int tid = threadIdx.x;
    sw[tid] = w_in[(size_t)b * N_DIM + tid];
    __syncthreads();

    const int m4 = tid & 31;   // float4 column
    const int q  = tid >> 5;   // n-stripe 0..15

    const float4* mb4 = (const float4*)(mem + (size_t)b * N_DIM * M_DIM)
                        + (size_t)q * 32 * 32;  // rows q*32 .. q*32+31

    float4 acc = make_float4(0.f, 0.f, 0.f, 0.f);
    #pragma unroll 4
    for (int i = 0; i < 32; i++) {
        const float wv  = sw[q * 32 + i];
        const float4 mv = mb4[i * 32 + m4];
        acc.x = fmaf(wv, mv.x, acc.x);
        acc.y = fmaf(wv, mv.y, acc.y);
        acc.z = fmaf(wv, mv.z, acc.z);
        acc.w = fmaf(wv, mv.w, acc.w);
    }
    sacc[q][m4] = acc;
    __syncthreads();

    if (q == 0) {
        float4 r = sacc[0][m4];
        #pragma unroll
        for (int s = 1; s < 16; s++) {
            float4 t = sacc[s][m4];
            r.x += t.x; r.y += t.y; r.z += t.z; r.w += t.w;
        }
        ((float4*)(read_out + (size_t)b * M_DIM))[m4] = r;
    }
}

// ============================================================================
extern "C" void kernel_launch(void* const* d_in, const int* in_sizes, int n_in,
                              void* d_out, int out_size)
{
    const float* ctrl   = (const float*)d_in[0];   // [512, 1024]
    const float* prev_w = (const float*)d_in[1];   // [512, 512]
    const float* mem    = (const float*)d_in[2];   // [512, 512, 128]
    const float* Wfc    = (const float*)d_in[3];   // [1024, 134]
    const float* bfc    = (const float*)d_in[4];   // [134]

    float* out      = (float*)d_out;
    float* read_out = out;                          // [512, 128]
    float* w_out    = out + B_DIM * M_DIM;          // [512, 512]

    fc_kernel<<<128, 288>>>(ctrl, Wfc, bfc);
    sim_kernel<<<8192, 256>>>(mem);
    addr_kernel<<<B_DIM, N_DIM>>>(prev_w, w_out);
    read_kernel<<<B_DIM, 512>>>(mem, w_out, read_out);
}

// round 14
// speedup vs baseline: 1.0033x; 1.0033x over previous
#include <cuda_runtime.h>
#include <math.h>

#define B_DIM 512
#define N_DIM 512
#define M_DIM 128
#define C_DIM 1024
#define ADDR  134
#define EPSV  1e-8f

// ---------------- scratch (device globals; no allocation allowed) ----------
__device__ float g_ks[B_DIM * M_DIM];     // beta * k / (||k||+EPS)
__device__ float g_gg[B_DIM];             // g (interpolation gate)
__device__ float g_ss[B_DIM * 3];         // shift softmax probs
__device__ float g_gamma[B_DIM];          // sharpening exponent
__device__ float g_z[B_DIM * N_DIM];      // beta * sim

__device__ __forceinline__ float softplus_f(float x) {
    return (x > 20.f) ? x : log1pf(expf(x));
}

// ============================================================================
// Kernel A: FC (4 batches / CTA, K split in 2 groups) + activations + key prep
// grid = 128, block = 288 (268 active: 2 K-groups x 134 columns)
// ============================================================================
__global__ __launch_bounds__(288) void fc_kernel(
    const float* __restrict__ ctrl,   // [B, C]
    const float* __restrict__ Wfc,    // [C, ADDR]
    const float* __restrict__ bfc)    // [ADDR]
{
    __shared__ float sctrl[4 * C_DIM];          // 16 KB
    __shared__ float spart[ADDR * 4];           // K-group partials
    __shared__ float sred[M_DIM * 4];           // ||k||^2 reduction
    __shared__ float sspec[4][6];               // beta,g,s0,s1,s2,gamma raw
    __shared__ float sscale[4];                 // beta/(||k||+EPS)

    const int tid = threadIdx.x;
    const int b0  = blockIdx.x * 4;

    // load 4 controller rows (contiguous) into smem
    const float* cb = ctrl + (size_t)b0 * C_DIM;
    for (int i = tid; i < 4 * C_DIM; i += 288) sctrl[i] = cb[i];
    __syncthreads();

    const bool active = (tid < 2 * ADDR);
    const int kg = (tid >= ADDR) ? 1 : 0;
    const int j  = tid - kg * ADDR;

    float acc[4] = {0.f, 0.f, 0.f, 0.f};
    if (active) {
        const int cbeg = kg * (C_DIM / 2);
        #pragma unroll 2
        for (int c4 = 0; c4 < (C_DIM / 2) / 4; c4++) {
            const int c = cbeg + c4 * 4;
            const float w0 = Wfc[(c + 0) * ADDR + j];
            const float w1 = Wfc[(c + 1) * ADDR + j];
            const float w2 = Wfc[(c + 2) * ADDR + j];
            const float w3 = Wfc[(c + 3) * ADDR + j];
            #pragma unroll
            for (int b = 0; b < 4; b++) {
                float4 cv = ((const float4*)(sctrl + b * C_DIM))[c / 4];
                acc[b] = fmaf(w0, cv.x, acc[b]);
                acc[b] = fmaf(w1, cv.y, acc[b]);
                acc[b] = fmaf(w2, cv.z, acc[b]);
                acc[b] = fmaf(w3, cv.w, acc[b]);
            }
        }
    }

    // combine the two K-groups
    if (active && kg == 1) {
        #pragma unroll
        for (int b = 0; b < 4; b++) spart[j * 4 + b] = acc[b];
    }
    __syncthreads();
    if (active && kg == 0) {
        const float bias = bfc[j];
        #pragma unroll
        for (int b = 0; b < 4; b++) acc[b] += spart[j * 4 + b] + bias;
        if (j < M_DIM) {
            #pragma unroll
            for (int b = 0; b < 4; b++) sred[j * 4 + b] = acc[b] * acc[b];
        } else {
            #pragma unroll
            for (int b = 0; b < 4; b++) sspec[b][j - M_DIM] = acc[b];
        }
    }
    __syncthreads();

    // reduce ||k||^2 per batch (tree over j, all threads hit the syncs)
    for (int off = 64; off > 0; off >>= 1) {
        if (active && kg == 0 && j < off) {
            #pragma unroll
            for (int b = 0; b < 4; b++)
                sred[j * 4 + b] += sred[(j + off) * 4 + b];
        }
        __syncthreads();
    }

    // per-batch scalar post-processing
    if (tid < 4) {
        const int b = tid;
        const float normk = sqrtf(sred[b]) + EPSV;
        const float beta  = softplus_f(sspec[b][0]);
        sscale[b] = beta / normk;
        g_gg[b0 + b] = 1.f / (1.f + expf(-sspec[b][1]));
        float l0 = sspec[b][2], l1 = sspec[b][3], l2 = sspec[b][4];
        float mx = fmaxf(l0, fmaxf(l1, l2));
        float e0 = expf(l0 - mx), e1 = expf(l1 - mx), e2 = expf(l2 - mx);
        float inv = 1.f / (e0 + e1 + e2);
        g_ss[(b0 + b) * 3 + 0] = e0 * inv;
        g_ss[(b0 + b) * 3 + 1] = e1 * inv;
        g_ss[(b0 + b) * 3 + 2] = e2 * inv;
        g_gamma[b0 + b] = 1.f + softplus_f(sspec[b][5]);
    }
    __syncthreads();

    // scaled key
    if (active && kg == 0 && j < M_DIM) {
        #pragma unroll
        for (int b = 0; b < 4; b++)
            g_ks[(size_t)(b0 + b) * M_DIM + j] = acc[b] * sscale[b];
    }
}

// ============================================================================
// Kernel B: z[b,n] = beta*sim = dot(mem[b,n,:], ks[b,:]) / (||mem[b,n,:]||+EPS)
// one warp -> 4 rows; grid = 8192, block = 256 (32 rows / CTA)
// ============================================================================
__global__ __launch_bounds__(256) void sim_kernel(const float* __restrict__ mem)
{
    const int lane = threadIdx.x & 31;
    const int warp = threadIdx.x >> 5;
    const int b  = blockIdx.x >> 4;                       // 16 blocks / batch
    const int n0 = ((blockIdx.x & 15) * 8 + warp) * 4;    // 4 rows / warp

    const float4 ks = ((const float4*)(g_ks + (size_t)b * M_DIM))[lane];
    const float4* mrow = (const float4*)(mem + ((size_t)b * N_DIM + n0) * M_DIM);

    float4 m0 = mrow[lane];
    float4 m1 = mrow[32 + lane];
    float4 m2 = mrow[64 + lane];
    float4 m3 = mrow[96 + lane];

    float d[4], q[4];
    d[0] = m0.x*ks.x + m0.y*ks.y + m0.z*ks.z + m0.w*ks.w;
    q[0] = m0.x*m0.x + m0.y*m0.y + m0.z*m0.z + m0.w*m0.w;
    d[1] = m1.x*ks.x + m1.y*ks.y + m1.z*ks.z + m1.w*ks.w;
    q[1] = m1.x*m1.x + m1.y*m1.y + m1.z*m1.z + m1.w*m1.w;
    d[2] = m2.x*ks.x + m2.y*ks.y + m2.z*ks.z + m2.w*ks.w;
    q[2] = m2.x*m2.x + m2.y*m2.y + m2.z*m2.z + m2.w*m2.w;
    d[3] = m3.x*ks.x + m3.y*ks.y + m3.z*ks.z + m3.w*ks.w;
    q[3] = m3.x*m3.x + m3.y*m3.y + m3.z*m3.z + m3.w*m3.w;

    #pragma unroll
    for (int r = 0; r < 4; r++) {
        #pragma unroll
        for (int off = 16; off > 0; off >>= 1) {
            d[r] += __shfl_xor_sync(0xffffffffu, d[r], off);
            q[r] += __shfl_xor_sync(0xffffffffu, q[r], off);
        }
    }
    if (lane == 0) {
        float* zp = g_z + (size_t)b * N_DIM + n0;
        zp[0] = d[0] / (sqrtf(q[0]) + EPSV);
        zp[1] = d[1] / (sqrtf(q[1]) + EPSV);
        zp[2] = d[2] / (sqrtf(q[2]) + EPSV);
        zp[3] = d[3] / (sqrtf(q[3]) + EPSV);
    }
}

// ---------------- block reductions (512 threads = 16 warps) ----------------
__device__ __forceinline__ float block_max512(float v, float* sbuf) {
    #pragma unroll
    for (int off = 16; off > 0; off >>= 1)
        v = fmaxf(v, __shfl_xor_sync(0xffffffffu, v, off));
    const int lane = threadIdx.x & 31, wp = threadIdx.x >> 5;
    if (lane == 0) sbuf[wp] = v;
    __syncthreads();
    if (wp == 0) {
        float x = (lane < 16) ? sbuf[lane] : -3.4e38f;
        #pragma unroll
        for (int off = 8; off > 0; off >>= 1)
            x = fmaxf(x, __shfl_xor_sync(0xffffffffu, x, off));
        if (lane == 0) sbuf[0] = x;
    }
    __syncthreads();
    float r = sbuf[0];
    __syncthreads();
    return r;
}

__device__ __forceinline__ float block_sum512(float v, float* sbuf) {
    #pragma unroll
    for (int off = 16; off > 0; off >>= 1)
        v += __shfl_xor_sync(0xffffffffu, v, off);
    const int lane = threadIdx.x & 31, wp = threadIdx.x >> 5;
    if (lane == 0) sbuf[wp] = v;
    __syncthreads();
    if (wp == 0) {
        float x = (lane < 16) ? sbuf[lane] : 0.f;
        #pragma unroll
        for (int off = 8; off > 0; off >>= 1)
            x += __shfl_xor_sync(0xffffffffu, x, off);
        if (lane == 0) sbuf[0] = x;
    }
    __syncthreads();
    float r = sbuf[0];
    __syncthreads();
    return r;
}

// ============================================================================
// Kernel C: softmax(z) -> interpolate -> circular shift -> sharpen -> w
// grid = 512 (batch), block = 512 (n)
// ============================================================================
__global__ __launch_bounds__(512) void addr_kernel(
    const float* __restrict__ prev_w,  // [B, N]
    float* __restrict__ out_w)         // [B, N] (region of d_out)
{
    __shared__ float swg[N_DIM];
    __shared__ float sbuf[16];

    const int b = blockIdx.x;
    const int n = threadIdx.x;

    float z = g_z[(size_t)b * N_DIM + n];
    const float zmax = block_max512(z, sbuf);
    float e = expf(z - zmax);
    const float esum = block_sum512(e, sbuf);
    const float wc = e / esum;

    const float g  = g_gg[b];
    const float wg = g * wc + (1.f - g) * prev_w[(size_t)b * N_DIM + n];
    swg[n] = wg;
    __syncthreads();

    const float s0 = g_ss[b * 3 + 0];
    const float s1 = g_ss[b * 3 + 1];
    const float s2 = g_ss[b * 3 + 2];
    const float ws = s0 * swg[(n + N_DIM - 1) & (N_DIM - 1)]
                   + s1 * wg
                   + s2 * swg[(n + 1) & (N_DIM - 1)];

    const float gamma = g_gamma[b];
    const float wp = powf(ws, gamma);
    const float denom = block_sum512(wp, sbuf) + EPSV;
    out_w[(size_t)b * N_DIM + n] = wp / denom;
}

// ============================================================================
// Kernel D: read_vec[b,m] = sum_n w[b,n] * mem[b,n,m]
// grid = 512 (batch), block = 512; 16 n-stripes x 32 float4 lanes
// ============================================================================
__global__ __launch_bounds__(512) void read_kernel(
    const float* __restrict__ mem,
    const float* __restrict__ w_in,     // [B, N]
    float* __restrict__ read_out)       // [B, M]
{
    __shared__ float  sw[N_DIM];
    __shared__ float4 sacc[16][32];

    const int b   = blockIdx.x;
    const int tid = threadIdx.x;
    sw[tid] = w_in[(size_t)b * N_DIM + tid];
    __syncthreads();

    const int m4 = tid & 31;   // float4 column
    const int q  = tid >> 5;   // n-stripe 0..15

    const float4* mb4 = (const float4*)(mem + (size_t)b * N_DIM * M_DIM)
                        + (size_t)q * 32 * 32;  // rows q*32 .. q*32+31

    float4 acc = make_float4(0.f, 0.f, 0.f, 0.f);
    #pragma unroll 4
    for (int i = 0; i < 32; i++) {
        const float wv  = sw[q * 32 + i];
        const float4 mv = mb4[i * 32 + m4];
        acc.x = fmaf(wv, mv.x, acc.x);
        acc.y = fmaf(wv, mv.y, acc.y);
        acc.z = fmaf(wv, mv.z, acc.z);
        acc.w = fmaf(wv, mv.w, acc.w);
    }
    sacc[q][m4] = acc;
    __syncthreads();

    if (q == 0) {
        float4 r = sacc[0][m4];
        #pragma unroll
        for (int s = 1; s < 16; s++) {
            float4 t = sacc[s][m4];
            r.x += t.x; r.y += t.y; r.z += t.z; r.w += t.w;
        }
        ((float4*)(read_out + (size_t)b * M_DIM))[m4] = r;
    }
}

// ============================================================================
extern "C" void kernel_launch(void* const* d_in, const int* in_sizes, int n_in,
                              void* d_out, int out_size)
{
    const float* ctrl   = (const float*)d_in[0];   // [512, 1024]
    const float* prev_w = (const float*)d_in[1];   // [512, 512]
    const float* mem    = (const float*)d_in[2];   // [512, 512, 128]
    const float* Wfc    = (const float*)d_in[3];   // [1024, 134]
    const float* bfc    = (const float*)d_in[4];   // [134]

    float* out      = (float*)d_out;
    float* read_out = out;                          // [512, 128]
    float* w_out    = out + B_DIM * M_DIM;          // [512, 512]

    fc_kernel<<<128, 288>>>(ctrl, Wfc, bfc);
    sim_kernel<<<8192, 256>>>(mem);
    addr_kernel<<<B_DIM, N_DIM>>>(prev_w, w_out);
    read_kernel<<<B_DIM, 512>>>(mem, w_out, read_out);
}

// round 15
// speedup vs baseline: 1.0582x; 1.0547x over previous
#include <cuda_runtime.h>
#include <math.h>

#define B_DIM 512
#define N_DIM 512
#define M_DIM 128
#define C_DIM 1024
#define ADDR  134
#define EPSV  1e-8f

// ---------------- scratch (device globals; no allocation allowed) ----------
__device__ float g_ks[B_DIM * M_DIM];     // beta * k / (||k||+EPS)
__device__ float g_gg[B_DIM];             // g (interpolation gate)
__device__ float g_ss[B_DIM * 3];         // shift softmax probs
__device__ float g_gamma[B_DIM];          // sharpening exponent

__device__ __forceinline__ float softplus_f(float x) {
    return (x > 20.f) ? x : log1pf(expf(x));
}

// ============================================================================
// Kernel A: FC (4 batches / CTA, K split in 2 groups) + activations + key prep
// grid = 128, block = 288 (268 active: 2 K-groups x 134 columns)
// ============================================================================
__global__ __launch_bounds__(288) void fc_kernel(
    const float* __restrict__ ctrl,   // [B, C]
    const float* __restrict__ Wfc,    // [C, ADDR]
    const float* __restrict__ bfc)    // [ADDR]
{
    __shared__ float sctrl[4 * C_DIM];          // 16 KB
    __shared__ float spart[ADDR * 4];           // K-group partials
    __shared__ float sred[M_DIM * 4];           // ||k||^2 reduction
    __shared__ float sspec[4][6];               // beta,g,s0,s1,s2,gamma raw
    __shared__ float sscale[4];                 // beta/(||k||+EPS)

    const int tid = threadIdx.x;
    const int b0  = blockIdx.x * 4;

    const float* cb = ctrl + (size_t)b0 * C_DIM;
    for (int i = tid; i < 4 * C_DIM; i += 288) sctrl[i] = cb[i];
    __syncthreads();

    const bool active = (tid < 2 * ADDR);
    const int kg = (tid >= ADDR) ? 1 : 0;
    const int j  = tid - kg * ADDR;

    float acc[4] = {0.f, 0.f, 0.f, 0.f};
    if (active) {
        const int cbeg = kg * (C_DIM / 2);
        #pragma unroll 2
        for (int c4 = 0; c4 < (C_DIM / 2) / 4; c4++) {
            const int c = cbeg + c4 * 4;
            const float w0 = Wfc[(c + 0) * ADDR + j];
            const float w1 = Wfc[(c + 1) * ADDR + j];
            const float w2 = Wfc[(c + 2) * ADDR + j];
            const float w3 = Wfc[(c + 3) * ADDR + j];
            #pragma unroll
            for (int b = 0; b < 4; b++) {
                float4 cv = ((const float4*)(sctrl + b * C_DIM))[c / 4];
                acc[b] = fmaf(w0, cv.x, acc[b]);
                acc[b] = fmaf(w1, cv.y, acc[b]);
                acc[b] = fmaf(w2, cv.z, acc[b]);
                acc[b] = fmaf(w3, cv.w, acc[b]);
            }
        }
    }

    if (active && kg == 1) {
        #pragma unroll
        for (int b = 0; b < 4; b++) spart[j * 4 + b] = acc[b];
    }
    __syncthreads();
    if (active && kg == 0) {
        const float bias = bfc[j];
        #pragma unroll
        for (int b = 0; b < 4; b++) acc[b] += spart[j * 4 + b] + bias;
        if (j < M_DIM) {
            #pragma unroll
            for (int b = 0; b < 4; b++) sred[j * 4 + b] = acc[b] * acc[b];
        } else {
            #pragma unroll
            for (int b = 0; b < 4; b++) sspec[b][j - M_DIM] = acc[b];
        }
    }
    __syncthreads();

    for (int off = 64; off > 0; off >>= 1) {
        if (active && kg == 0 && j < off) {
            #pragma unroll
            for (int b = 0; b < 4; b++)
                sred[j * 4 + b] += sred[(j + off) * 4 + b];
        }
        __syncthreads();
    }

    if (tid < 4) {
        const int b = tid;
        const float normk = sqrtf(sred[b]) + EPSV;
        const float beta  = softplus_f(sspec[b][0]);
        sscale[b] = beta / normk;
        g_gg[b0 + b] = 1.f / (1.f + expf(-sspec[b][1]));
        float l0 = sspec[b][2], l1 = sspec[b][3], l2 = sspec[b][4];
        float mx = fmaxf(l0, fmaxf(l1, l2));
        float e0 = expf(l0 - mx), e1 = expf(l1 - mx), e2 = expf(l2 - mx);
        float inv = 1.f / (e0 + e1 + e2);
        g_ss[(b0 + b) * 3 + 0] = e0 * inv;
        g_ss[(b0 + b) * 3 + 1] = e1 * inv;
        g_ss[(b0 + b) * 3 + 2] = e2 * inv;
        g_gamma[b0 + b] = 1.f + softplus_f(sspec[b][5]);
    }
    __syncthreads();

    if (active && kg == 0 && j < M_DIM) {
        #pragma unroll
        for (int b = 0; b < 4; b++)
            g_ks[(size_t)(b0 + b) * M_DIM + j] = acc[b] * sscale[b];
    }
}

// ---------------- block reductions (512 threads = 16 warps) ----------------
__device__ __forceinline__ float block_max512(float v, float* sbuf) {
    #pragma unroll
    for (int off = 16; off > 0; off >>= 1)
        v = fmaxf(v, __shfl_xor_sync(0xffffffffu, v, off));
    const int lane = threadIdx.x & 31, wp = threadIdx.x >> 5;
    if (lane == 0) sbuf[wp] = v;
    __syncthreads();
    if (wp == 0) {
        float x = (lane < 16) ? sbuf[lane] : -3.4e38f;
        #pragma unroll
        for (int off = 8; off > 0; off >>= 1)
            x = fmaxf(x, __shfl_xor_sync(0xffffffffu, x, off));
        if (lane == 0) sbuf[0] = x;
    }
    __syncthreads();
    float r = sbuf[0];
    __syncthreads();
    return r;
}

__device__ __forceinline__ float block_sum512(float v, float* sbuf) {
    #pragma unroll
    for (int off = 16; off > 0; off >>= 1)
        v += __shfl_xor_sync(0xffffffffu, v, off);
    const int lane = threadIdx.x & 31, wp = threadIdx.x >> 5;
    if (lane == 0) sbuf[wp] = v;
    __syncthreads();
    if (wp == 0) {
        float x = (lane < 16) ? sbuf[lane] : 0.f;
        #pragma unroll
        for (int off = 8; off > 0; off >>= 1)
            x += __shfl_xor_sync(0xffffffffu, x, off);
        if (lane == 0) sbuf[0] = x;
    }
    __syncthreads();
    float r = sbuf[0];
    __syncthreads();
    return r;
}

// ============================================================================
// Fused kernel: per-batch  sim -> softmax -> interpolate/shift/sharpen -> read
// grid = 512 (one batch per CTA), block = 512, max 2 CTAs/SM.
// Pass 2 re-reads the batch's 256KB memory slice shortly after pass 1 streamed
// it; concurrent wave footprint (~296 CTAs x 256KB = 74MB) fits in L2, so the
// second sweep is served from L2 instead of DRAM.
// ============================================================================
__global__ __launch_bounds__(512, 2) void fused_kernel(
    const float* __restrict__ mem,     // [B, N, M]
    const float* __restrict__ prev_w,  // [B, N]
    float* __restrict__ w_out,         // [B, N]
    float* __restrict__ read_out)      // [B, M]
{
    __shared__ float  sz[N_DIM];
    __shared__ float  swg[N_DIM];
    __shared__ float  sw[N_DIM];
    __shared__ float  sbuf[16];
    __shared__ float4 sacc[16][32];

    const int b    = blockIdx.x;
    const int tid  = threadIdx.x;
    const int lane = tid & 31;
    const int wp   = tid >> 5;           // warp 0..15

    const float4* mb4 = (const float4*)(mem + (size_t)b * N_DIM * M_DIM);

    // ---------- pass 1: z[n] = beta * cosine_sim -------------------------
    {
        const float4 ks4 = ((const float4*)(g_ks + (size_t)b * M_DIM))[lane];
        const float4* mrow = mb4 + (size_t)(wp * 32) * 32;   // 32 rows / warp

        #pragma unroll
        for (int i0 = 0; i0 < 32; i0 += 4) {
            float4 m0 = mrow[(i0 + 0) * 32 + lane];
            float4 m1 = mrow[(i0 + 1) * 32 + lane];
            float4 m2 = mrow[(i0 + 2) * 32 + lane];
            float4 m3 = mrow[(i0 + 3) * 32 + lane];

            float d0 = m0.x*ks4.x + m0.y*ks4.y + m0.z*ks4.z + m0.w*ks4.w;
            float q0 = m0.x*m0.x + m0.y*m0.y + m0.z*m0.z + m0.w*m0.w;
            float d1 = m1.x*ks4.x + m1.y*ks4.y + m1.z*ks4.z + m1.w*ks4.w;
            float q1 = m1.x*m1.x + m1.y*m1.y + m1.z*m1.z + m1.w*m1.w;
            float d2 = m2.x*ks4.x + m2.y*ks4.y + m2.z*ks4.z + m2.w*ks4.w;
            float q2 = m2.x*m2.x + m2.y*m2.y + m2.z*m2.z + m2.w*m2.w;
            float d3 = m3.x*ks4.x + m3.y*ks4.y + m3.z*ks4.z + m3.w*ks4.w;
            float q3 = m3.x*m3.x + m3.y*m3.y + m3.z*m3.z + m3.w*m3.w;

            #pragma unroll
            for (int off = 16; off > 0; off >>= 1) {
                d0 += __shfl_xor_sync(0xffffffffu, d0, off);
                q0 += __shfl_xor_sync(0xffffffffu, q0, off);
                d1 += __shfl_xor_sync(0xffffffffu, d1, off);
                q1 += __shfl_xor_sync(0xffffffffu, q1, off);
                d2 += __shfl_xor_sync(0xffffffffu, d2, off);
                q2 += __shfl_xor_sync(0xffffffffu, q2, off);
                d3 += __shfl_xor_sync(0xffffffffu, d3, off);
                q3 += __shfl_xor_sync(0xffffffffu, q3, off);
            }
            if (lane == 0) {
                const int n0 = wp * 32 + i0;
                sz[n0 + 0] = d0 / (sqrtf(q0) + EPSV);
                sz[n0 + 1] = d1 / (sqrtf(q1) + EPSV);
                sz[n0 + 2] = d2 / (sqrtf(q2) + EPSV);
                sz[n0 + 3] = d3 / (sqrtf(q3) + EPSV);
            }
        }
    }
    __syncthreads();

    // ---------- addressing: softmax -> interpolate -> shift -> sharpen ---
    {
        const int n = tid;
        float z = sz[n];
        const float zmax = block_max512(z, sbuf);
        float e = expf(z - zmax);
        const float esum = block_sum512(e, sbuf);
        const float wc = e / esum;

        const float g  = g_gg[b];
        const float wg = g * wc + (1.f - g) * prev_w[(size_t)b * N_DIM + n];
        swg[n] = wg;
        __syncthreads();

        const float s0 = g_ss[b * 3 + 0];
        const float s1 = g_ss[b * 3 + 1];
        const float s2 = g_ss[b * 3 + 2];
        const float ws = s0 * swg[(n + N_DIM - 1) & (N_DIM - 1)]
                       + s1 * wg
                       + s2 * swg[(n + 1) & (N_DIM - 1)];

        const float gamma = g_gamma[b];
        const float wpw = powf(ws, gamma);
        const float denom = block_sum512(wpw, sbuf) + EPSV;
        const float w = wpw / denom;
        sw[n] = w;
        w_out[(size_t)b * N_DIM + n] = w;
    }
    __syncthreads();

    // ---------- pass 2: read_vec[m] = sum_n w[n] * mem[n, m] -------------
    {
        const int m4 = tid & 31;   // float4 column
        const int q  = tid >> 5;   // n-stripe 0..15

        const float4* ms = mb4 + (size_t)q * 32 * 32;  // rows q*32 .. q*32+31

        float4 acc = make_float4(0.f, 0.f, 0.f, 0.f);
        #pragma unroll 4
        for (int i = 0; i < 32; i++) {
            const float wv  = sw[q * 32 + i];
            const float4 mv = ms[i * 32 + m4];
            acc.x = fmaf(wv, mv.x, acc.x);
            acc.y = fmaf(wv, mv.y, acc.y);
            acc.z = fmaf(wv, mv.z, acc.z);
            acc.w = fmaf(wv, mv.w, acc.w);
        }
        sacc[q][m4] = acc;
        __syncthreads();

        if (q == 0) {
            float4 r = sacc[0][m4];
            #pragma unroll
            for (int s = 1; s < 16; s++) {
                float4 t = sacc[s][m4];
                r.x += t.x; r.y += t.y; r.z += t.z; r.w += t.w;
            }
            ((float4*)(read_out + (size_t)b * M_DIM))[m4] = r;
        }
    }
}

// ============================================================================
extern "C" void kernel_launch(void* const* d_in, const int* in_sizes, int n_in,
                              void* d_out, int out_size)
{
    const float* ctrl   = (const float*)d_in[0];   // [512, 1024]
    const float* prev_w = (const float*)d_in[1];   // [512, 512]
    const float* mem    = (const float*)d_in[2];   // [512, 512, 128]
    const float* Wfc    = (const float*)d_in[3];   // [1024, 134]
    const float* bfc    = (const float*)d_in[4];   // [134]

    float* out      = (float*)d_out;
    float* read_out = out;                          // [512, 128]
    float* w_out    = out + B_DIM * M_DIM;          // [512, 512]

    fc_kernel<<<128, 288>>>(ctrl, Wfc, bfc);
    fused_kernel<<<B_DIM, 512>>>(mem, prev_w, w_out, read_out);
}

// round 16
// speedup vs baseline: 1.0607x; 1.0024x over previous
#include <cuda_runtime.h>
#include <math.h>

#define B_DIM 512
#define N_DIM 512
#define M_DIM 128
#define C_DIM 1024
#define ADDR  134
#define EPSV  1e-8f

// ---------------- scratch (device globals; no allocation allowed) ----------
__device__ float g_ks[B_DIM * M_DIM];     // beta * k / (||k||+EPS)
__device__ float g_gg[B_DIM];             // g (interpolation gate)
__device__ float g_ss[B_DIM * 3];         // shift softmax probs
__device__ float g_gamma[B_DIM];          // sharpening exponent

__device__ __forceinline__ float softplus_f(float x) {
    return (x > 20.f) ? x : log1pf(expf(x));
}

// ============================================================================
// Kernel A: FC (4 batches / CTA, K split in 2 groups) + activations + key prep
// grid = 128, block = 288 (268 active: 2 K-groups x 134 columns)
// ============================================================================
__global__ __launch_bounds__(288) void fc_kernel(
    const float* __restrict__ ctrl,   // [B, C]
    const float* __restrict__ Wfc,    // [C, ADDR]
    const float* __restrict__ bfc)    // [ADDR]
{
    __shared__ float sctrl[4 * C_DIM];          // 16 KB
    __shared__ float spart[ADDR * 4];           // K-group partials
    __shared__ float sred[M_DIM * 4];           // ||k||^2 reduction
    __shared__ float sspec[4][6];               // beta,g,s0,s1,s2,gamma raw
    __shared__ float sscale[4];                 // beta/(||k||+EPS)

    const int tid = threadIdx.x;
    const int b0  = blockIdx.x * 4;

    const float* cb = ctrl + (size_t)b0 * C_DIM;
    for (int i = tid; i < 4 * C_DIM; i += 288) sctrl[i] = cb[i];
    __syncthreads();

    const bool active = (tid < 2 * ADDR);
    const int kg = (tid >= ADDR) ? 1 : 0;
    const int j  = tid - kg * ADDR;

    float acc[4] = {0.f, 0.f, 0.f, 0.f};
    if (active) {
        const int cbeg = kg * (C_DIM / 2);
        #pragma unroll 2
        for (int c4 = 0; c4 < (C_DIM / 2) / 4; c4++) {
            const int c = cbeg + c4 * 4;
            const float w0 = Wfc[(c + 0) * ADDR + j];
            const float w1 = Wfc[(c + 1) * ADDR + j];
            const float w2 = Wfc[(c + 2) * ADDR + j];
            const float w3 = Wfc[(c + 3) * ADDR + j];
            #pragma unroll
            for (int b = 0; b < 4; b++) {
                float4 cv = ((const float4*)(sctrl + b * C_DIM))[c / 4];
                acc[b] = fmaf(w0, cv.x, acc[b]);
                acc[b] = fmaf(w1, cv.y, acc[b]);
                acc[b] = fmaf(w2, cv.z, acc[b]);
                acc[b] = fmaf(w3, cv.w, acc[b]);
            }
        }
    }

    if (active && kg == 1) {
        #pragma unroll
        for (int b = 0; b < 4; b++) spart[j * 4 + b] = acc[b];
    }
    __syncthreads();
    if (active && kg == 0) {
        const float bias = bfc[j];
        #pragma unroll
        for (int b = 0; b < 4; b++) acc[b] += spart[j * 4 + b] + bias;
        if (j < M_DIM) {
            #pragma unroll
            for (int b = 0; b < 4; b++) sred[j * 4 + b] = acc[b] * acc[b];
        } else {
            #pragma unroll
            for (int b = 0; b < 4; b++) sspec[b][j - M_DIM] = acc[b];
        }
    }
    __syncthreads();

    for (int off = 64; off > 0; off >>= 1) {
        if (active && kg == 0 && j < off) {
            #pragma unroll
            for (int b = 0; b < 4; b++)
                sred[j * 4 + b] += sred[(j + off) * 4 + b];
        }
        __syncthreads();
    }

    if (tid < 4) {
        const int b = tid;
        const float normk = sqrtf(sred[b]) + EPSV;
        const float beta  = softplus_f(sspec[b][0]);
        sscale[b] = beta / normk;
        g_gg[b0 + b] = 1.f / (1.f + expf(-sspec[b][1]));
        float l0 = sspec[b][2], l1 = sspec[b][3], l2 = sspec[b][4];
        float mx = fmaxf(l0, fmaxf(l1, l2));
        float e0 = expf(l0 - mx), e1 = expf(l1 - mx), e2 = expf(l2 - mx);
        float inv = 1.f / (e0 + e1 + e2);
        g_ss[(b0 + b) * 3 + 0] = e0 * inv;
        g_ss[(b0 + b) * 3 + 1] = e1 * inv;
        g_ss[(b0 + b) * 3 + 2] = e2 * inv;
        g_gamma[b0 + b] = 1.f + softplus_f(sspec[b][5]);
    }
    __syncthreads();

    if (active && kg == 0 && j < M_DIM) {
        #pragma unroll
        for (int b = 0; b < 4; b++)
            g_ks[(size_t)(b0 + b) * M_DIM + j] = acc[b] * sscale[b];
    }
}

// ---------------- block reductions (512 threads = 16 warps) ----------------
__device__ __forceinline__ float block_max512(float v, float* sbuf) {
    #pragma unroll
    for (int off = 16; off > 0; off >>= 1)
        v = fmaxf(v, __shfl_xor_sync(0xffffffffu, v, off));
    const int lane = threadIdx.x & 31, wp = threadIdx.x >> 5;
    if (lane == 0) sbuf[wp] = v;
    __syncthreads();
    if (wp == 0) {
        float x = (lane < 16) ? sbuf[lane] : -3.4e38f;
        #pragma unroll
        for (int off = 8; off > 0; off >>= 1)
            x = fmaxf(x, __shfl_xor_sync(0xffffffffu, x, off));
        if (lane == 0) sbuf[0] = x;
    }
    __syncthreads();
    float r = sbuf[0];
    __syncthreads();
    return r;
}

__device__ __forceinline__ float block_sum512(float v, float* sbuf) {
    #pragma unroll
    for (int off = 16; off > 0; off >>= 1)
        v += __shfl_xor_sync(0xffffffffu, v, off);
    const int lane = threadIdx.x & 31, wp = threadIdx.x >> 5;
    if (lane == 0) sbuf[wp] = v;
    __syncthreads();
    if (wp == 0) {
        float x = (lane < 16) ? sbuf[lane] : 0.f;
        #pragma unroll
        for (int off = 8; off > 0; off >>= 1)
            x += __shfl_xor_sync(0xffffffffu, x, off);
        if (lane == 0) sbuf[0] = x;
    }
    __syncthreads();
    float r = sbuf[0];
    __syncthreads();
    return r;
}

// ============================================================================
// Fused kernel: per-batch  sim -> softmax -> interpolate/shift/sharpen -> read
// grid = 512 (one batch per CTA), block = 512, max 2 CTAs/SM.
// Pass 2 re-reads the batch's 256KB memory slice shortly after pass 1 streamed
// it; concurrent wave footprint (~296 CTAs x 256KB = 74MB) fits in L2, so the
// second sweep is served from L2 instead of DRAM.
// ============================================================================
__global__ __launch_bounds__(512, 2) void fused_kernel(
    const float* __restrict__ mem,     // [B, N, M]
    const float* __restrict__ prev_w,  // [B, N]
    float* __restrict__ w_out,         // [B, N]
    float* __restrict__ read_out)      // [B, M]
{
    __shared__ float  sz[N_DIM];
    __shared__ float  swg[N_DIM];
    __shared__ float  sw[N_DIM];
    __shared__ float  sbuf[16];
    __shared__ float4 sacc[16][32];

    const int b    = blockIdx.x;
    const int tid  = threadIdx.x;
    const int lane = tid & 31;
    const int wp   = tid >> 5;           // warp 0..15

    const float4* mb4 = (const float4*)(mem + (size_t)b * N_DIM * M_DIM);

    // ---------- pass 1: z[n] = beta * cosine_sim -------------------------
    {
        const float4 ks4 = ((const float4*)(g_ks + (size_t)b * M_DIM))[lane];
        const float4* mrow = mb4 + (size_t)(wp * 32) * 32;   // 32 rows / warp

        #pragma unroll
        for (int i0 = 0; i0 < 32; i0 += 4) {
            float4 m0 = mrow[(i0 + 0) * 32 + lane];
            float4 m1 = mrow[(i0 + 1) * 32 + lane];
            float4 m2 = mrow[(i0 + 2) * 32 + lane];
            float4 m3 = mrow[(i0 + 3) * 32 + lane];

            float d0 = m0.x*ks4.x + m0.y*ks4.y + m0.z*ks4.z + m0.w*ks4.w;
            float q0 = m0.x*m0.x + m0.y*m0.y + m0.z*m0.z + m0.w*m0.w;
            float d1 = m1.x*ks4.x + m1.y*ks4.y + m1.z*ks4.z + m1.w*ks4.w;
            float q1 = m1.x*m1.x + m1.y*m1.y + m1.z*m1.z + m1.w*m1.w;
            float d2 = m2.x*ks4.x + m2.y*ks4.y + m2.z*ks4.z + m2.w*ks4.w;
            float q2 = m2.x*m2.x + m2.y*m2.y + m2.z*m2.z + m2.w*m2.w;
            float d3 = m3.x*ks4.x + m3.y*ks4.y + m3.z*ks4.z + m3.w*ks4.w;
            float q3 = m3.x*m3.x + m3.y*m3.y + m3.z*m3.z + m3.w*m3.w;

            #pragma unroll
            for (int off = 16; off > 0; off >>= 1) {
                d0 += __shfl_xor_sync(0xffffffffu, d0, off);
                q0 += __shfl_xor_sync(0xffffffffu, q0, off);
                d1 += __shfl_xor_sync(0xffffffffu, d1, off);
                q1 += __shfl_xor_sync(0xffffffffu, q1, off);
                d2 += __shfl_xor_sync(0xffffffffu, d2, off);
                q2 += __shfl_xor_sync(0xffffffffu, q2, off);
                d3 += __shfl_xor_sync(0xffffffffu, d3, off);
                q3 += __shfl_xor_sync(0xffffffffu, q3, off);
            }
            if (lane == 0) {
                const int n0 = wp * 32 + i0;
                sz[n0 + 0] = d0 / (sqrtf(q0) + EPSV);
                sz[n0 + 1] = d1 / (sqrtf(q1) + EPSV);
                sz[n0 + 2] = d2 / (sqrtf(q2) + EPSV);
                sz[n0 + 3] = d3 / (sqrtf(q3) + EPSV);
            }
        }
    }
    __syncthreads();

    // ---------- addressing: softmax -> interpolate -> shift -> sharpen ---
    {
        const int n = tid;
        float z = sz[n];
        const float zmax = block_max512(z, sbuf);
        float e = expf(z - zmax);
        const float esum = block_sum512(e, sbuf);
        const float wc = e / esum;

        const float g  = g_gg[b];
        const float wg = g * wc + (1.f - g) * prev_w[(size_t)b * N_DIM + n];
        swg[n] = wg;
        __syncthreads();

        const float s0 = g_ss[b * 3 + 0];
        const float s1 = g_ss[b * 3 + 1];
        const float s2 = g_ss[b * 3 + 2];
        const float ws = s0 * swg[(n + N_DIM - 1) & (N_DIM - 1)]
                       + s1 * wg
                       + s2 * swg[(n + 1) & (N_DIM - 1)];

        const float gamma = g_gamma[b];
        const float wpw = powf(ws, gamma);
        const float denom = block_sum512(wpw, sbuf) + EPSV;
        const float w = wpw / denom;
        sw[n] = w;
        w_out[(size_t)b * N_DIM + n] = w;
    }
    __syncthreads();

    // ---------- pass 2: read_vec[m] = sum_n w[n] * mem[n, m] -------------
    {
        const int m4 = tid & 31;   // float4 column
        const int q  = tid >> 5;   // n-stripe 0..15

        const float4* ms = mb4 + (size_t)q * 32 * 32;  // rows q*32 .. q*32+31

        float4 acc = make_float4(0.f, 0.f, 0.f, 0.f);
        #pragma unroll 4
        for (int i = 0; i < 32; i++) {
            const float wv  = sw[q * 32 + i];
            const float4 mv = ms[i * 32 + m4];
            acc.x = fmaf(wv, mv.x, acc.x);
            acc.y = fmaf(wv, mv.y, acc.y);
            acc.z = fmaf(wv, mv.z, acc.z);
            acc.w = fmaf(wv, mv.w, acc.w);
        }
        sacc[q][m4] = acc;
        __syncthreads();

        if (q == 0) {
            float4 r = sacc[0][m4];
            #pragma unroll
            for (int s = 1; s < 16; s++) {
                float4 t = sacc[s][m4];
                r.x += t.x; r.y += t.y; r.z += t.z; r.w += t.w;
            }
            ((float4*)(read_out + (size_t)b * M_DIM))[m4] = r;
        }
    }
}

// ============================================================================
extern "C" void kernel_launch(void* const* d_in, const int* in_sizes, int n_in,
                              void* d_out, int out_size)
{
    const float* ctrl   = (const float*)d_in[0];   // [512, 1024]
    const float* prev_w = (const float*)d_in[1];   // [512, 512]
    const float* mem    = (const float*)d_in[2];   // [512, 512, 128]
    const float* Wfc    = (const float*)d_in[3];   // [1024, 134]
    const float* bfc    = (const float*)d_in[4];   // [134]

    float* out      = (float*)d_out;
    float* read_out = out;                          // [512, 128]
    float* w_out    = out + B_DIM * M_DIM;          // [512, 512]

    fc_kernel<<<128, 288>>>(ctrl, Wfc, bfc);
    fused_kernel<<<B_DIM, 512>>>(mem, prev_w, w_out, read_out);
}